// round 14
// baseline (speedup 1.0000x reference)
#include <cuda_runtime.h>
#include <cuda_bf16.h>
#include <math.h>
#include <stdint.h>

// Problem constants (fixed shapes)
#define T_TOK   16384
#define DMODEL  512
#define HDIM    1024
#define NEXP    8
#define NDISP   (T_TOK * 2)              // T * top_k
#define PAD_CAP (NDISP + NEXP * 128)     // per-expert padding to 128-row tiles
#define MAXTILES ((NDISP / 128) + NEXP)  // 264
#define NT1 (MAXTILES * 8)               // GEMM1 tasks (8 n-tiles, K=512)
#define NT2 (MAXTILES * 8)               // GEMM2 tasks (4 n-tiles x 2 k-chunks)
#define SMEM_DYN (8 * 8 * 128 * 4 * 2)   // As + Bs, 8-stage ring = 65536 B

// ---------------- scratch (device globals; no allocations) ----------------
__device__ float g_h[(size_t)PAD_CAP * HDIM];   // GEMM1 output (post-GELU)
__device__ float g_zero[DMODEL];                // zero row for padded gathers
__device__ int   g_row_disp[PAD_CAP];           // padded row -> dispatch idx (or -1)
__device__ float g_row_scale[PAD_CAP];          // gate score per padded row
__device__ int   g_expert_of[NDISP];
__device__ float g_scale_of[NDISP];
__device__ int   g_count[NEXP];
__device__ int   g_cursor[NEXP];
__device__ int   g_pad_off[NEXP];
__device__ int   g_tile_start[NEXP + 1];
__device__ int   g_task_ctr;
__device__ int   g_done[MAXTILES];

// ---------------- packed f32x2 helpers ----------------
#define PACKDUP(dst, xf)                                               \
    asm("mov.b64 %0, {%1, %1};" : "=l"(dst) : "r"(__float_as_uint(xf)))

#define FMA2(acc, a2, b2)                                              \
    asm("fma.rn.f32x2 %0, %1, %2, %0;" : "+l"(acc) : "l"(a2), "l"(b2))

#define UNPACK2F(xf, yf, src)                                          \
    do {                                                               \
        uint32_t u0_, u1_;                                             \
        asm("mov.b64 {%0, %1}, %2;" : "=r"(u0_), "=r"(u1_) : "l"(src));\
        xf = __uint_as_float(u0_);                                     \
        yf = __uint_as_float(u1_);                                     \
    } while (0)

// ---------------- init: reset control state only ----------------
__global__ void init_kernel() {
    int i = blockIdx.x * blockDim.x + threadIdx.x;
    if (i < PAD_CAP) { g_row_disp[i] = -1; g_row_scale[i] = 0.f; }
    if (i < NEXP)    { g_count[i] = 0; g_cursor[i] = 0; }
    if (i < MAXTILES) g_done[i] = 0;
    if (i == 0) g_task_ctr = 0;
}

// ---------------- gating: logits -> top2 -> softmax; also zeroes out ----------------
__global__ void gate_kernel(const float* __restrict__ x,
                            const float* __restrict__ gw,
                            const float* __restrict__ gb,
                            float* __restrict__ out) {
    __shared__ int s_cnt[NEXP];
    int warp = threadIdx.x >> 5, lane = threadIdx.x & 31;
    int t = blockIdx.x * 8 + warp;   // grid = T_TOK/8 blocks of 256 -> exact

    // zero the output buffer (grid covers exactly: 2048 blocks * 256 thr * 4 float4)
    {
        size_t zi = (size_t)blockIdx.x * 256 + threadIdx.x;
        float4 z4 = make_float4(0.f, 0.f, 0.f, 0.f);
        float4* o4 = (float4*)out;
#pragma unroll
        for (int q = 0; q < 4; q++)
            o4[zi + (size_t)q * (T_TOK / 8 * 256)] = z4;
    }

    if (threadIdx.x < NEXP) s_cnt[threadIdx.x] = 0;
    __syncthreads();

    float acc[NEXP];
#pragma unroll
    for (int e = 0; e < NEXP; e++) acc[e] = 0.f;

    const float* xr = x + (size_t)t * DMODEL;
    for (int i = lane; i < DMODEL; i += 32) {
        float xv = xr[i];
        const float4* g4 = (const float4*)(gw + (size_t)i * NEXP);
        float4 a = g4[0], b = g4[1];
        acc[0] += xv * a.x; acc[1] += xv * a.y; acc[2] += xv * a.z; acc[3] += xv * a.w;
        acc[4] += xv * b.x; acc[5] += xv * b.y; acc[6] += xv * b.z; acc[7] += xv * b.w;
    }
#pragma unroll
    for (int e = 0; e < NEXP; e++) {
#pragma unroll
        for (int off = 16; off > 0; off >>= 1)
            acc[e] += __shfl_xor_sync(0xFFFFFFFFu, acc[e], off);
    }

    if (lane == 0) {
        float v0 = -1e30f, v1 = -1e30f; int i0 = 0, i1 = 0;
#pragma unroll
        for (int e = 0; e < NEXP; e++) {
            float v = acc[e] + gb[e];
            if (v > v0) { v1 = v0; i1 = i0; v0 = v; i0 = e; }
            else if (v > v1) { v1 = v; i1 = e; }
        }
        float ed = expf(v1 - v0);
        float inv = 1.f / (1.f + ed);
        g_expert_of[2 * t + 0] = i0; g_scale_of[2 * t + 0] = inv;
        g_expert_of[2 * t + 1] = i1; g_scale_of[2 * t + 1] = ed * inv;
        atomicAdd(&s_cnt[i0], 1);
        atomicAdd(&s_cnt[i1], 1);
    }
    __syncthreads();
    if (threadIdx.x < NEXP && s_cnt[threadIdx.x] > 0)
        atomicAdd(&g_count[threadIdx.x], s_cnt[threadIdx.x]);
}

// ---------------- padded offsets ----------------
__global__ void offsets_kernel() {
    if (threadIdx.x == 0) {
        int off = 0, ts = 0;
        for (int e = 0; e < NEXP; e++) {
            g_pad_off[e] = off;
            g_tile_start[e] = ts;
            int tiles = (g_count[e] + 127) >> 7;
            ts += tiles;
            off += tiles * 128;
        }
        g_tile_start[NEXP] = ts;
    }
}

// ---------------- scatter dispatches into padded rows (block-aggregated) ----------------
__global__ void scatter_kernel() {
    __shared__ int s_cnt[NEXP];
    __shared__ int s_base[NEXP];
    int j = blockIdx.x * blockDim.x + threadIdx.x;  // exact: NDISP/256 blocks

    if (threadIdx.x < NEXP) s_cnt[threadIdx.x] = 0;
    __syncthreads();

    int e = g_expert_of[j];
    int lpos = atomicAdd(&s_cnt[e], 1);
    __syncthreads();

    if (threadIdx.x < NEXP) {
        int c = s_cnt[threadIdx.x];
        s_base[threadIdx.x] = (c > 0) ? atomicAdd(&g_cursor[threadIdx.x], c) : 0;
    }
    __syncthreads();

    int r = g_pad_off[e] + s_base[e] + lpos;
    g_row_disp[r] = j;
    g_row_scale[r] = g_scale_of[j];
}

__device__ __forceinline__ float gelu_exact(float v) {
    return 0.5f * v * (1.f + erff(v * 0.70710678118654752440f));
}

// ---------------- GEMM task body: 128x128x512 (KT=64), FMA2, 8-stage ring, sync/4kt ----------------
// ROWSTRIDE = full K of this layer (= A row stride = W k-dim). KLEN per task = 512.
// LAYER2 epilogue atomicAdds (c + bias*bflag) * scale into out[token].
template <int ROWSTRIDE, int NLD, bool LAYER1>
__device__ __forceinline__ void gemm_tile_body(
    int row_base, int e, int n0, int koff, float bflag,
    const float* __restrict__ X, const float* __restrict__ W,
    const float* __restrict__ Bv, float* __restrict__ out,
    float* As, float* Bs, const float** Aptr)
{
    const int tid = threadIdx.x;
    if (tid < 128) {
        if (LAYER1) {
            int j = g_row_disp[row_base + tid];
            Aptr[tid] = (j >= 0) ? (X + (size_t)(j >> 1) * ROWSTRIDE) : g_zero;
        } else {
            Aptr[tid] = g_h + (size_t)(row_base + tid) * ROWSTRIDE;
        }
    }
    __syncthreads();

    const float* Wb = W + ((size_t)e * ROWSTRIDE + koff) * NLD + n0;
    const int arow = tid >> 1, ahalf = tid & 1;
    const int brow = tid >> 5, bchunk = tid & 31;
    const float* aSrc = Aptr[arow] + koff + ahalf * 4;
    const float* bSrc = Wb + (size_t)brow * NLD + bchunk * 4;
    const int tx = tid & 15, ty = tid >> 4;

    uint64_t acc[8][4];
#pragma unroll
    for (int i = 0; i < 8; i++)
#pragma unroll
        for (int jp = 0; jp < 4; jp++) acc[i][jp] = 0ull;

    const int KT = 64;   // 512 / 8

#define STORE_STAGE_V(sbuf, av, bv)                                         \
    do {                                                                    \
        As[((sbuf) * 8 + ahalf * 4 + 0) * 128 + arow] = (av).x;             \
        As[((sbuf) * 8 + ahalf * 4 + 1) * 128 + arow] = (av).y;             \
        As[((sbuf) * 8 + ahalf * 4 + 2) * 128 + arow] = (av).z;             \
        As[((sbuf) * 8 + ahalf * 4 + 3) * 128 + arow] = (av).w;             \
        *(float4*)&Bs[((sbuf) * 8 + brow) * 128 + bchunk * 4] = (bv);       \
    } while (0)

    // prologue: fill stages 0..3 with MLP=4 batched loads
    {
        float4 pa[4], pb[4];
#pragma unroll
        for (int s = 0; s < 4; s++) {
            pa[s] = *(const float4*)(aSrc + s * 8);
            pb[s] = *(const float4*)(bSrc + (size_t)s * 8 * NLD);
        }
#pragma unroll
        for (int s = 0; s < 4; s++) STORE_STAGE_V(s, pa[s], pb[s]);
    }
    __syncthreads();

    float4 aReg, bReg;
    for (int kt = 0; kt < KT; ++kt) {
        if (kt > 0 && (kt & 3) == 0) __syncthreads();   // window boundary

        if (kt + 4 < KT) {
            aReg = *(const float4*)(aSrc + (kt + 4) * 8);
            bReg = *(const float4*)(bSrc + (size_t)(kt + 4) * 8 * NLD);
        }

        const int buf = kt & 7;
#pragma unroll
        for (int kk = 0; kk < 8; ++kk) {
            const float* aRow = As + (buf * 8 + kk) * 128;
            const float* bRow = Bs + (buf * 8 + kk) * 128;
            float4 a0 = *(const float4*)(aRow + ty * 4);
            float4 a1 = *(const float4*)(aRow + 64 + ty * 4);
            ulonglong2 bv0 = *(const ulonglong2*)(bRow + tx * 4);
            ulonglong2 bv1 = *(const ulonglong2*)(bRow + 64 + tx * 4);

            uint64_t aa;
            PACKDUP(aa, a0.x);
            FMA2(acc[0][0], aa, bv0.x); FMA2(acc[0][1], aa, bv0.y);
            FMA2(acc[0][2], aa, bv1.x); FMA2(acc[0][3], aa, bv1.y);
            PACKDUP(aa, a0.y);
            FMA2(acc[1][0], aa, bv0.x); FMA2(acc[1][1], aa, bv0.y);
            FMA2(acc[1][2], aa, bv1.x); FMA2(acc[1][3], aa, bv1.y);
            PACKDUP(aa, a0.z);
            FMA2(acc[2][0], aa, bv0.x); FMA2(acc[2][1], aa, bv0.y);
            FMA2(acc[2][2], aa, bv1.x); FMA2(acc[2][3], aa, bv1.y);
            PACKDUP(aa, a0.w);
            FMA2(acc[3][0], aa, bv0.x); FMA2(acc[3][1], aa, bv0.y);
            FMA2(acc[3][2], aa, bv1.x); FMA2(acc[3][3], aa, bv1.y);
            PACKDUP(aa, a1.x);
            FMA2(acc[4][0], aa, bv0.x); FMA2(acc[4][1], aa, bv0.y);
            FMA2(acc[4][2], aa, bv1.x); FMA2(acc[4][3], aa, bv1.y);
            PACKDUP(aa, a1.y);
            FMA2(acc[5][0], aa, bv0.x); FMA2(acc[5][1], aa, bv0.y);
            FMA2(acc[5][2], aa, bv1.x); FMA2(acc[5][3], aa, bv1.y);
            PACKDUP(aa, a1.z);
            FMA2(acc[6][0], aa, bv0.x); FMA2(acc[6][1], aa, bv0.y);
            FMA2(acc[6][2], aa, bv1.x); FMA2(acc[6][3], aa, bv1.y);
            PACKDUP(aa, a1.w);
            FMA2(acc[7][0], aa, bv0.x); FMA2(acc[7][1], aa, bv0.y);
            FMA2(acc[7][2], aa, bv1.x); FMA2(acc[7][3], aa, bv1.y);
        }

        if (kt + 4 < KT) STORE_STAGE_V((kt + 4) & 7, aReg, bReg);
    }
#undef STORE_STAGE_V

    __syncthreads();   // final-stage reads done before next task reuses smem

    // ---------------- epilogue ----------------
    float bias[8];
#pragma unroll
    for (int j = 0; j < 4; j++) {
        bias[j]     = Bv[(size_t)e * NLD + n0 + tx * 4 + j] * bflag;
        bias[j + 4] = Bv[(size_t)e * NLD + n0 + 64 + tx * 4 + j] * bflag;
    }
#pragma unroll
    for (int ii = 0; ii < 8; ++ii) {
        int rloc = (ii < 4) ? (ty * 4 + ii) : (64 + ty * 4 + (ii - 4));
        int r = row_base + rloc;
        float c[8];
        UNPACK2F(c[0], c[1], acc[ii][0]);
        UNPACK2F(c[2], c[3], acc[ii][1]);
        UNPACK2F(c[4], c[5], acc[ii][2]);
        UNPACK2F(c[6], c[7], acc[ii][3]);
        if (LAYER1) {
            float* dst = g_h + (size_t)r * NLD + n0;
            float4 o0, o1;
            o0.x = gelu_exact(c[0] + bias[0]);
            o0.y = gelu_exact(c[1] + bias[1]);
            o0.z = gelu_exact(c[2] + bias[2]);
            o0.w = gelu_exact(c[3] + bias[3]);
            o1.x = gelu_exact(c[4] + bias[4]);
            o1.y = gelu_exact(c[5] + bias[5]);
            o1.z = gelu_exact(c[6] + bias[6]);
            o1.w = gelu_exact(c[7] + bias[7]);
            *(float4*)(dst + tx * 4) = o0;
            *(float4*)(dst + 64 + tx * 4) = o1;
        } else {
            int j = g_row_disp[r];
            if (j >= 0) {
                float s = g_row_scale[r];
                float* dst = out + (size_t)(j >> 1) * DMODEL + n0;
#pragma unroll
                for (int q = 0; q < 4; q++)
                    atomicAdd(dst + tx * 4 + q, (c[q] + bias[q]) * s);
#pragma unroll
                for (int q = 0; q < 4; q++)
                    atomicAdd(dst + 64 + tx * 4 + q, (c[4 + q] + bias[4 + q]) * s);
            }
        }
    }
}

// ---------------- fused persistent GEMM1+GEMM2 kernel ----------------
__global__ __launch_bounds__(256, 2) void fused_gemm_kernel(
    const float* __restrict__ x,
    const float* __restrict__ w1, const float* __restrict__ b1,
    const float* __restrict__ w2, const float* __restrict__ b2,
    float* __restrict__ out)
{
    extern __shared__ __align__(16) float sdyn[];
    float* As = sdyn;                    // 8*8*128 floats
    float* Bs = sdyn + 8 * 8 * 128;      // 8*8*128 floats
    __shared__ const float* Aptr[128];
    __shared__ int s_task;

    for (;;) {
        __syncthreads();   // smem reuse safety + previous task complete
        if (threadIdx.x == 0) s_task = atomicAdd(&g_task_ctr, 1);
        __syncthreads();
        int task = s_task;
        if (task >= NT1 + NT2) return;

        int ts_end = g_tile_start[NEXP];

        if (task < NT1) {
            // GEMM1 tile (K = 512 in one task)
            int rt = task >> 3;
            int n0 = (task & 7) * 128;
            if (rt >= ts_end) continue;
            int e = 0;
            while (e < NEXP - 1 && g_tile_start[e + 1] <= rt) e++;
            int row_base = g_pad_off[e] + (rt - g_tile_start[e]) * 128;
            gemm_tile_body<DMODEL, HDIM, true>(row_base, e, n0, 0, 1.f,
                                               x, w1, b1, out, As, Bs, Aptr);
            __threadfence();
            __syncthreads();
            if (threadIdx.x == 0) atomicAdd(&g_done[rt], 1);
        } else {
            // GEMM2 half-K task (waits for its row-tile's 8 GEMM1 tiles)
            int t2 = task - NT1;
            int rt = t2 >> 3;
            int sub = t2 & 7;
            int n0 = (sub & 3) * 128;
            int koff = (sub >> 2) * 512;
            if (rt >= ts_end) continue;
            if (threadIdx.x == 0) {
                while (*(volatile int*)&g_done[rt] < 8) __nanosleep(64);
                __threadfence();
            }
            __syncthreads();
            int e = 0;
            while (e < NEXP - 1 && g_tile_start[e + 1] <= rt) e++;
            int row_base = g_pad_off[e] + (rt - g_tile_start[e]) * 128;
            gemm_tile_body<HDIM, DMODEL, false>(row_base, e, n0, koff,
                                                (koff == 0) ? 1.f : 0.f,
                                                nullptr, w2, b2, out, As, Bs, Aptr);
        }
    }
}

// ---------------- launch ----------------
extern "C" void kernel_launch(void* const* d_in, const int* in_sizes, int n_in,
                              void* d_out, int out_size) {
    const float* x      = (const float*)d_in[0];
    const float* gate_w = (const float*)d_in[1];
    const float* gate_b = (const float*)d_in[2];
    const float* w1     = (const float*)d_in[3];
    const float* b1     = (const float*)d_in[4];
    const float* w2     = (const float*)d_in[5];
    const float* b2     = (const float*)d_in[6];
    float* out = (float*)d_out;

    cudaFuncSetAttribute(fused_gemm_kernel,
                         cudaFuncAttributeMaxDynamicSharedMemorySize, SMEM_DYN);

    init_kernel<<<(PAD_CAP + 255) / 256, 256>>>();
    gate_kernel<<<T_TOK / 8, 256>>>(x, gate_w, gate_b, out);
    offsets_kernel<<<1, 32>>>();
    scatter_kernel<<<NDISP / 256, 256>>>();
    fused_gemm_kernel<<<296, 256, SMEM_DYN>>>(x, w1, b1, w2, b2, out);
}